// round 1
// baseline (speedup 1.0000x reference)
#include <cuda_runtime.h>
#include <cstdint>

#define ATOM_DIM 128
#define EDGE_DIM 64
#define N_NODES_MAX 50000
#define N_EDGES_MAX 800000

// ---------------- scratch (static __device__ arrays; no allocation) ----------
// Es|Eg interleaved per edge: 256 floats/edge  (819 MB)
__device__ float g_edgebuf[(size_t)N_EDGES_MAX * 256];
// Ps|Pg|Qs|Qg interleaved per node: 512 floats/node (102 MB)
__device__ float g_nodebuf[(size_t)N_NODES_MAX * 512];
__device__ float g_acc[(size_t)N_NODES_MAX * ATOM_DIM];   // x + running segment sum
__device__ float g_x[(size_t)N_NODES_MAX * ATOM_DIM];     // current node features
__device__ float g_W4[128 * 512];   // packed node weights [Ka_s | Ka_g | Kb_s | Kb_g]
__device__ float g_We[64 * 256];    // packed edge weights [Ke_s | Ke_g]

// ---------------- math helpers ----------------------------------------------
__device__ __forceinline__ float fsigmoid(float x) {
    return 1.0f / (1.0f + __expf(-x));
}
__device__ __forceinline__ float fsoftplus(float x) {
    // log1p(exp(x)) stable form; abs error ~1e-7, well inside 1e-3 budget
    return fmaxf(x, 0.0f) + __logf(1.0f + __expf(-fabsf(x)));
}

// ---------------- weight packing ---------------------------------------------
// g_W4[k][j], k<128:  j<128 -> kernel_s[k][j]        (Ka_s)
//                     j<256 -> kernel_g[k][j-128]    (Ka_g)
//                     j<384 -> kernel_s[128+k][j-256](Kb_s)
//                     else  -> kernel_g[128+k][j-384](Kb_g)
// g_We[k][j], k<64 :  j<128 -> kernel_s[256+k][j] else kernel_g[256+k][j-128]
__global__ void pack_weights(const float* __restrict__ ks, const float* __restrict__ kg)
{
    int i = blockIdx.x * blockDim.x + threadIdx.x;
    if (i < 128 * 512) {
        int k = i >> 9;
        int j = i & 511;
        float v;
        if      (j < 128) v = ks[k * 128 + j];
        else if (j < 256) v = kg[k * 128 + (j - 128)];
        else if (j < 384) v = ks[(128 + k) * 128 + (j - 256)];
        else              v = kg[(128 + k) * 128 + (j - 384)];
        g_W4[i] = v;
    } else {
        int m = i - 128 * 512;
        if (m < 64 * 256) {
            int k = m >> 8;
            int j = m & 255;
            g_We[m] = (j < 128) ? ks[(256 + k) * 128 + j]
                                : kg[(256 + k) * 128 + (j - 128)];
        }
    }
}

// ---------------- fp32 tiled GEMM  C[M,N] = A[M,K] @ B[K,N] (+ bias) ---------
// BM=128, BN=64, BK=16, TM=8, TN=4, 256 threads.
#define BM 128
#define BN 64
#define BKK 16
#define TM 8
#define TN 4

__global__ __launch_bounds__(256, 2)
void sgemm(const float* __restrict__ A, const float* __restrict__ B,
           float* __restrict__ C,
           const float* __restrict__ bias_lo, const float* __restrict__ bias_hi,
           int has_bias, int M, int N, int K)
{
    __shared__ float As[BKK][BM];
    __shared__ float Bs[BKK][BN];

    int t  = threadIdx.x;
    int tx = t & 15;          // 0..15 -> column group (TN=4 cols each)
    int ty = t >> 4;          // 0..15 -> row group   (TM=8 rows each)
    int block_m = blockIdx.x * BM;
    int block_n = blockIdx.y * BN;

    // A tile load mapping: row = t/2 (0..127), 8 consecutive k per thread
    int a_row = t >> 1;
    int a_col = (t & 1) * 8;
    // B tile load mapping: row = t/16 (0..15), 4 consecutive n per thread
    int b_row = t >> 4;
    int b_col = (t & 15) * 4;

    float acc[TM][TN];
#pragma unroll
    for (int i = 0; i < TM; i++)
#pragma unroll
        for (int j = 0; j < TN; j++) acc[i][j] = 0.0f;

    for (int k0 = 0; k0 < K; k0 += BKK) {
        // ---- load A tile (transposed into As[k][m]) ----
        {
            int gm = block_m + a_row;
            float4 av0, av1;
            if (gm < M) {
                const float4* ap = (const float4*)(A + (size_t)gm * K + k0 + a_col);
                av0 = ap[0];
                av1 = ap[1];
            } else {
                av0 = make_float4(0.f, 0.f, 0.f, 0.f);
                av1 = av0;
            }
            As[a_col + 0][a_row] = av0.x;
            As[a_col + 1][a_row] = av0.y;
            As[a_col + 2][a_row] = av0.z;
            As[a_col + 3][a_row] = av0.w;
            As[a_col + 4][a_row] = av1.x;
            As[a_col + 5][a_row] = av1.y;
            As[a_col + 6][a_row] = av1.z;
            As[a_col + 7][a_row] = av1.w;
        }
        // ---- load B tile (K,N both multiples of tile dims: no guard) ----
        {
            float4 bv = *(const float4*)(B + (size_t)(k0 + b_row) * N + block_n + b_col);
            *(float4*)&Bs[b_row][b_col] = bv;
        }
        __syncthreads();

#pragma unroll
        for (int kk = 0; kk < BKK; kk++) {
            float ra[TM], rb[TN];
#pragma unroll
            for (int i = 0; i < TM; i++) ra[i] = As[kk][ty * TM + i];
#pragma unroll
            for (int j = 0; j < TN; j++) rb[j] = Bs[kk][tx * TN + j];
#pragma unroll
            for (int i = 0; i < TM; i++)
#pragma unroll
                for (int j = 0; j < TN; j++)
                    acc[i][j] += ra[i] * rb[j];
        }
        __syncthreads();
    }

    // ---- epilogue ----
    int NH = N >> 1;
#pragma unroll
    for (int i = 0; i < TM; i++) {
        int gm = block_m + ty * TM + i;
        if (gm >= M) continue;
        int gn0 = block_n + tx * TN;
        float4 o;
        o.x = acc[i][0];
        o.y = acc[i][1];
        o.z = acc[i][2];
        o.w = acc[i][3];
        if (has_bias) {
            float b0 = (gn0 + 0 < NH) ? bias_lo[gn0 + 0] : bias_hi[gn0 + 0 - NH];
            float b1 = (gn0 + 1 < NH) ? bias_lo[gn0 + 1] : bias_hi[gn0 + 1 - NH];
            float b2 = (gn0 + 2 < NH) ? bias_lo[gn0 + 2] : bias_hi[gn0 + 2 - NH];
            float b3 = (gn0 + 3 < NH) ? bias_lo[gn0 + 3] : bias_hi[gn0 + 3 - NH];
            o.x += b0; o.y += b1; o.z += b2; o.w += b3;
        }
        *(float4*)&C[(size_t)gm * N + gn0] = o;
    }
}

// ---------------- init: x = acc = atom_features -------------------------------
__global__ void init_xa(const float* __restrict__ af, int n4)
{
    int i = blockIdx.x * blockDim.x + threadIdx.x;
    if (i < n4) {
        float4 v = ((const float4*)af)[i];
        ((float4*)g_x)[i]   = v;
        ((float4*)g_acc)[i] = v;
    }
}

// ---------------- per-edge message + scatter-add ------------------------------
// One warp per edge; lane l handles features [4l, 4l+4).
__global__ void edge_msg(const int* __restrict__ pairs, int n_edges)
{
    int e = blockIdx.x * 8 + (threadIdx.x >> 5);
    if (e >= n_edges) return;
    int lane = threadIdx.x & 31;

    int src = pairs[2 * e];
    int dst = pairs[2 * e + 1];

    const float4* nb = (const float4*)g_nodebuf;   // node row = 128 float4
    const float4* eb = (const float4*)g_edgebuf;   // edge row = 64 float4

    size_t sb = (size_t)src * 128;
    size_t db = (size_t)dst * 128;
    size_t ebase = (size_t)e * 64;

    float4 ps = nb[sb + lane];            // Ps[src]
    float4 pg = nb[sb + 32 + lane];       // Pg[src]
    float4 qs = nb[db + 64 + lane];       // Qs[dst]
    float4 qg = nb[db + 96 + lane];       // Qg[dst]
    float4 es = eb[ebase + lane];         // Es[e] (bias_s folded in)
    float4 eg = eb[ebase + 32 + lane];    // Eg[e] (bias_g folded in)

    float4 m;
    m.x = fsigmoid(ps.x + qs.x + es.x) * fsoftplus(pg.x + qg.x + eg.x);
    m.y = fsigmoid(ps.y + qs.y + es.y) * fsoftplus(pg.y + qg.y + eg.y);
    m.z = fsigmoid(ps.z + qs.z + es.z) * fsoftplus(pg.z + qg.z + eg.z);
    m.w = fsigmoid(ps.w + qs.w + es.w) * fsoftplus(pg.w + qg.w + eg.w);

    float* dp = g_acc + (size_t)src * ATOM_DIM + lane * 4;
    asm volatile("red.global.add.v4.f32 [%0], {%1, %2, %3, %4};"
                 :: "l"(dp), "f"(m.x), "f"(m.y), "f"(m.z), "f"(m.w)
                 : "memory");
}

// ---------------- finish: softplus of acc -------------------------------------
__global__ void finish(float* __restrict__ out, int n4, int is_final)
{
    int i = blockIdx.x * blockDim.x + threadIdx.x;
    if (i < n4) {
        float4 a = ((const float4*)g_acc)[i];
        float4 v;
        v.x = fsoftplus(a.x);
        v.y = fsoftplus(a.y);
        v.z = fsoftplus(a.z);
        v.w = fsoftplus(a.w);
        if (is_final) {
            ((float4*)out)[i] = v;
        } else {
            ((float4*)g_x)[i]   = v;
            ((float4*)g_acc)[i] = v;   // re-init accumulator with new x
        }
    }
}

// ---------------- launch -------------------------------------------------------
extern "C" void kernel_launch(void* const* d_in, const int* in_sizes, int n_in,
                              void* d_out, int out_size)
{
    const float* atom  = (const float*)d_in[0];  // (n_nodes, 128)
    const float* esph  = (const float*)d_in[1];  // (n_edges, 64)
    const float* ks    = (const float*)d_in[3];  // (320, 128)
    const float* bs    = (const float*)d_in[4];  // (128,)
    const float* kg    = (const float*)d_in[5];  // (320, 128)
    const float* bg    = (const float*)d_in[6];  // (128,)
    const int*   pairs = (const int*)d_in[7];    // (n_edges, 2) int32

    int n_nodes = in_sizes[0] / ATOM_DIM;
    int n_edges = in_sizes[1] / EDGE_DIM;

    float *p_edgebuf, *p_nodebuf, *p_x, *p_W4, *p_We;
    cudaGetSymbolAddress((void**)&p_edgebuf, g_edgebuf);
    cudaGetSymbolAddress((void**)&p_nodebuf, g_nodebuf);
    cudaGetSymbolAddress((void**)&p_x,       g_x);
    cudaGetSymbolAddress((void**)&p_W4,      g_W4);
    cudaGetSymbolAddress((void**)&p_We,      g_We);

    // 1) pack weights
    pack_weights<<<(128 * 512 + 64 * 256 + 255) / 256, 256>>>(ks, kg);

    // 2) precompute edge contributions (step-invariant): Es|Eg + bias
    {
        dim3 grid((n_edges + BM - 1) / BM, 256 / BN);
        sgemm<<<grid, 256>>>(esph, p_We, p_edgebuf, bs, bg, 1, n_edges, 256, EDGE_DIM);
    }

    // 3) init x and acc
    int n4 = n_nodes * (ATOM_DIM / 4);
    init_xa<<<(n4 + 255) / 256, 256>>>(atom, n4);

    // 4) three message-passing steps
    for (int s = 0; s < 3; s++) {
        dim3 grid((n_nodes + BM - 1) / BM, 512 / BN);
        sgemm<<<grid, 256>>>(p_x, p_W4, p_nodebuf, nullptr, nullptr, 0,
                             n_nodes, 512, ATOM_DIM);
        edge_msg<<<(n_edges + 7) / 8, 256>>>(pairs, n_edges);
        finish<<<(n4 + 255) / 256, 256>>>((float*)d_out, n4, s == 2 ? 1 : 0);
    }
}

// round 6
// speedup vs baseline: 1.9402x; 1.9402x over previous
#include <cuda_runtime.h>
#include <cuda_fp16.h>
#include <cstdint>

#define ATOM_DIM 128
#define N_NODES_PAD 50048          // 391 * 128, padded so node GEMM tiles need no guards
#define N_EDGES_MAX 800000

// ---------------- scratch (static __device__ arrays; no allocation) ----------
__device__ __half g_edgebuf[(size_t)N_EDGES_MAX * 256];   // [Es|Eg] per edge, fp16 (410 MB)
__device__ __half g_nodebuf[(size_t)N_NODES_PAD * 512];   // [Ps|Pg|Qs|Qg] per node, fp16 (51 MB)
__device__ float  g_acc[(size_t)N_NODES_PAD * ATOM_DIM];  // x + running segment sum (f32)
__device__ float  g_x[(size_t)N_NODES_PAD * ATOM_DIM];    // current node features (f32, padded rows stay 0)
__device__ __half g_W4T[512 * 128];   // node weights, transposed [N=512][K=128], fp16
__device__ __half g_WeT[256 * 64];    // edge weights, transposed [N=256][K=64], fp16
__device__ float  g_biasPk[256];      // [bias_s | bias_g] (f32)

// ---------------- math helpers ----------------------------------------------
__device__ __forceinline__ float fsigmoid(float x) {
    return 1.0f / (1.0f + __expf(-x));
}
__device__ __forceinline__ float fsoftplus(float x) {
    return fmaxf(x, 0.0f) + __logf(1.0f + __expf(-fabsf(x)));
}
__device__ __forceinline__ uint32_t smem_to_u32(const void* p) {
    uint32_t a;
    asm("{ .reg .u64 t; cvta.to.shared.u64 t, %1; cvt.u32.u64 %0, t; }" : "=r"(a) : "l"(p));
    return a;
}
__device__ __forceinline__ uint32_t h2_bits(__half2 h) {
    uint32_t u;
    __builtin_memcpy(&u, &h, 4);
    return u;
}

// ---------------- weight packing (transpose + fp16) --------------------------
// g_W4T[n][k] (n<512,k<128): n<128 -> ks[k][n]; n<256 -> kg[k][n-128];
//                             n<384 -> ks[128+k][n-256]; else kg[128+k][n-384]
// g_WeT[n][k] (n<256,k<64): n<128 -> ks[256+k][n]; else kg[256+k][n-128]
__global__ void pack_weights(const float* __restrict__ ks, const float* __restrict__ kg,
                             const float* __restrict__ bs, const float* __restrict__ bg)
{
    int i = blockIdx.x * blockDim.x + threadIdx.x;
    if (i < 512 * 128) {
        int n = i >> 7, k = i & 127;
        float v;
        if      (n < 128) v = ks[k * 128 + n];
        else if (n < 256) v = kg[k * 128 + (n - 128)];
        else if (n < 384) v = ks[(128 + k) * 128 + (n - 256)];
        else              v = kg[(128 + k) * 128 + (n - 384)];
        g_W4T[i] = __float2half_rn(v);
    } else if (i < 512 * 128 + 256 * 64) {
        int m = i - 512 * 128;
        int n = m >> 6, k = m & 63;
        float v = (n < 128) ? ks[(256 + k) * 128 + n] : kg[(256 + k) * 128 + (n - 128)];
        g_WeT[m] = __float2half_rn(v);
    } else if (i < 512 * 128 + 256 * 64 + 256) {
        int n = i - (512 * 128 + 256 * 64);
        g_biasPk[n] = (n < 128) ? bs[n] : bg[n - 128];
    }
}

// ---------------- mma.sync fp16 GEMM -----------------------------------------
// C[M, NDIM] (fp16) = A[M, KDIM] (f32) @ BT^T  (BT: [NDIM][KDIM] fp16, K-major).
// CTA: 128 rows x 128-col chunks, K unrolled fully in smem. 8 warps (2 M x 4 N),
// warp tile 64x32, mma m16n8k16 f32-accum. Swizzled smem + ldmatrix.
template <int KDIM, int NDIM, bool BIAS>
__global__ __launch_bounds__(256)
void gemm_mma(const float* __restrict__ A, const __half* __restrict__ BT,
              __half* __restrict__ C, const float* __restrict__ bias)
{
    constexpr int ROWB   = KDIM * 2;        // bytes per smem row
    constexpr int KQ     = KDIM / 4;        // float4s per A row
    constexpr int KC     = KDIM / 16;       // k-chunks per mma pass
    constexpr int NCHUNK = NDIM / 128;
    constexpr int A_BYTES = 128 * ROWB;

    extern __shared__ char smem[];
    char* smA = smem;
    char* smB = smem + A_BYTES;
    float* smBias = (float*)(smem + 2 * A_BYTES);

    const int tid  = threadIdx.x;
    const int wid  = tid >> 5;
    const int lane = tid & 31;
    const int wm   = wid & 1;       // M half: 0/1  -> rows 0/64
    const int wn   = wid >> 1;      // N quarter within chunk: 0..3 -> cols 0/32/64/96
    const int m0   = blockIdx.x * 128;

    // ---- load A tile: f32 -> fp16, swizzled ----
    for (int i = tid; i < 128 * KQ; i += 256) {
        int r = i / KQ;
        int q = i - r * KQ;
        float4 v = *(const float4*)(A + (size_t)(m0 + r) * KDIM + q * 4);
        __half2 h01 = __floats2half2_rn(v.x, v.y);
        __half2 h23 = __floats2half2_rn(v.z, v.w);
        int chunk = q >> 1;
        int off   = (q & 1) * 8;
        int sw    = chunk ^ (r & 7);
        uint2 u;
        u.x = h2_bits(h01);
        u.y = h2_bits(h23);
        *(uint2*)(smA + r * ROWB + sw * 16 + off) = u;
    }
    if (BIAS) {
        for (int i = tid; i < NDIM; i += 256) smBias[i] = bias[i];
    }

    const uint32_t smA32 = smem_to_u32(smA);
    const uint32_t smB32 = smem_to_u32(smB);

    for (int nc = 0; nc < NCHUNK; nc++) {
        if (nc > 0) __syncthreads();   // all warps done with previous B chunk
        // ---- load B chunk (already fp16): rows nc*128 .. +128 ----
        for (int i = tid; i < 128 * KQ; i += 256) {
            int r = i / KQ;
            int q = i - r * KQ;
            uint2 u = *(const uint2*)(BT + (size_t)(nc * 128 + r) * KDIM + q * 4);
            int chunk = q >> 1;
            int off   = (q & 1) * 8;
            int sw    = chunk ^ (r & 7);
            *(uint2*)(smB + r * ROWB + sw * 16 + off) = u;
        }
        __syncthreads();

        float acc[4][4][4];
#pragma unroll
        for (int a = 0; a < 4; a++)
#pragma unroll
            for (int b = 0; b < 4; b++)
#pragma unroll
                for (int c = 0; c < 4; c++) acc[a][b][c] = 0.0f;

#pragma unroll
        for (int kc = 0; kc < KC; kc++) {
            // per-lane ldmatrix address pieces
            int lrow16 = lane & 15;           // row within 16-row block
            int khalf  = lane >> 4;           // 0: k-low 8, 1: k-high 8
            int chunkI = kc * 2 + khalf;

            uint32_t afr[4][4];
#pragma unroll
            for (int mt = 0; mt < 4; mt++) {
                int row = wm * 64 + mt * 16 + lrow16;
                int sw  = chunkI ^ (row & 7);
                uint32_t addr = smA32 + row * ROWB + sw * 16;
                asm volatile("ldmatrix.sync.aligned.m8n8.x4.shared.b16 {%0,%1,%2,%3}, [%4];"
                             : "=r"(afr[mt][0]), "=r"(afr[mt][1]),
                               "=r"(afr[mt][2]), "=r"(afr[mt][3])
                             : "r"(addr));
            }
            uint32_t bfr[2][4];
#pragma unroll
            for (int p = 0; p < 2; p++) {
                int nrow = wn * 32 + p * 16 + lrow16;
                int sw   = chunkI ^ (nrow & 7);
                uint32_t addr = smB32 + nrow * ROWB + sw * 16;
                asm volatile("ldmatrix.sync.aligned.m8n8.x4.shared.b16 {%0,%1,%2,%3}, [%4];"
                             : "=r"(bfr[p][0]), "=r"(bfr[p][1]),
                               "=r"(bfr[p][2]), "=r"(bfr[p][3])
                             : "r"(addr));
            }
#pragma unroll
            for (int mt = 0; mt < 4; mt++) {
#pragma unroll
                for (int nt = 0; nt < 4; nt++) {
                    uint32_t b0 = bfr[nt >> 1][(nt & 1)];
                    uint32_t b1 = bfr[nt >> 1][2 + (nt & 1)];
                    asm volatile(
                        "mma.sync.aligned.m16n8k16.row.col.f32.f16.f16.f32 "
                        "{%0,%1,%2,%3}, {%4,%5,%6,%7}, {%8,%9}, {%0,%1,%2,%3};"
                        : "+f"(acc[mt][nt][0]), "+f"(acc[mt][nt][1]),
                          "+f"(acc[mt][nt][2]), "+f"(acc[mt][nt][3])
                        : "r"(afr[mt][0]), "r"(afr[mt][1]),
                          "r"(afr[mt][2]), "r"(afr[mt][3]),
                          "r"(b0), "r"(b1));
                }
            }
        }

        // ---- epilogue: fp16 store ----
#pragma unroll
        for (int mt = 0; mt < 4; mt++) {
            int row0 = m0 + wm * 64 + mt * 16 + (lane >> 2);
            int row1 = row0 + 8;
#pragma unroll
            for (int nt = 0; nt < 4; nt++) {
                int colg = nc * 128 + wn * 32 + nt * 8 + (lane & 3) * 2;
                float c0 = acc[mt][nt][0], c1 = acc[mt][nt][1];
                float c2 = acc[mt][nt][2], c3 = acc[mt][nt][3];
                if (BIAS) {
                    float b0 = smBias[colg], b1 = smBias[colg + 1];
                    c0 += b0; c1 += b1; c2 += b0; c3 += b1;
                }
                *(__half2*)(C + (size_t)row0 * NDIM + colg) = __floats2half2_rn(c0, c1);
                *(__half2*)(C + (size_t)row1 * NDIM + colg) = __floats2half2_rn(c2, c3);
            }
        }
    }
}

// ---------------- init: x = acc = atom_features -------------------------------
__global__ void init_xa(const float* __restrict__ af, int n4)
{
    int i = blockIdx.x * blockDim.x + threadIdx.x;
    if (i < n4) {
        float4 v = ((const float4*)af)[i];
        ((float4*)g_x)[i]   = v;
        ((float4*)g_acc)[i] = v;
    }
}

// ---------------- per-edge message + scatter-add (fp16 inputs) ---------------
// One warp per edge; lane l handles features [4l, 4l+4).
__device__ __forceinline__ void ld4h(const __half2* p, float2& a, float2& b)
{
    uint2 u = *(const uint2*)p;
    __half2 ha, hb;
    __builtin_memcpy(&ha, &u.x, 4);
    __builtin_memcpy(&hb, &u.y, 4);
    a = __half22float2(ha);
    b = __half22float2(hb);
}

__global__ void edge_msg(const int* __restrict__ pairs, int n_edges)
{
    int e = blockIdx.x * 8 + (threadIdx.x >> 5);
    if (e >= n_edges) return;
    int lane = threadIdx.x & 31;

    int src = pairs[2 * e];
    int dst = pairs[2 * e + 1];

    const __half2* nb = (const __half2*)g_nodebuf;   // node row = 256 half2
    const __half2* eb = (const __half2*)g_edgebuf;   // edge row = 128 half2
    size_t sb  = (size_t)src * 256;
    size_t db  = (size_t)dst * 256;
    size_t ebb = (size_t)e * 128;
    int l2 = lane * 2;

    float2 ps0, ps1, pg0, pg1, qs0, qs1, qg0, qg1, es0, es1, eg0, eg1;
    ld4h(nb + sb + l2,        ps0, ps1);   // Ps[src]
    ld4h(nb + sb + 64 + l2,   pg0, pg1);   // Pg[src]
    ld4h(nb + db + 128 + l2,  qs0, qs1);   // Qs[dst]
    ld4h(nb + db + 192 + l2,  qg0, qg1);   // Qg[dst]
    ld4h(eb + ebb + l2,       es0, es1);   // Es[e] (bias_s folded)
    ld4h(eb + ebb + 64 + l2,  eg0, eg1);   // Eg[e] (bias_g folded)

    float4 m;
    m.x = fsigmoid(ps0.x + qs0.x + es0.x) * fsoftplus(pg0.x + qg0.x + eg0.x);
    m.y = fsigmoid(ps0.y + qs0.y + es0.y) * fsoftplus(pg0.y + qg0.y + eg0.y);
    m.z = fsigmoid(ps1.x + qs1.x + es1.x) * fsoftplus(pg1.x + qg1.x + eg1.x);
    m.w = fsigmoid(ps1.y + qs1.y + es1.y) * fsoftplus(pg1.y + qg1.y + eg1.y);

    float* dp = g_acc + (size_t)src * ATOM_DIM + lane * 4;
    asm volatile("red.global.add.v4.f32 [%0], {%1, %2, %3, %4};"
                 :: "l"(dp), "f"(m.x), "f"(m.y), "f"(m.z), "f"(m.w)
                 : "memory");
}

// ---------------- finish: softplus of acc -------------------------------------
__global__ void finish(float* __restrict__ out, int n4, int is_final)
{
    int i = blockIdx.x * blockDim.x + threadIdx.x;
    if (i < n4) {
        float4 a = ((const float4*)g_acc)[i];
        float4 v;
        v.x = fsoftplus(a.x);
        v.y = fsoftplus(a.y);
        v.z = fsoftplus(a.z);
        v.w = fsoftplus(a.w);
        if (is_final) {
            ((float4*)out)[i] = v;
        } else {
            ((float4*)g_x)[i]   = v;
            ((float4*)g_acc)[i] = v;
        }
    }
}

// ---------------- launch -------------------------------------------------------
extern "C" void kernel_launch(void* const* d_in, const int* in_sizes, int n_in,
                              void* d_out, int out_size)
{
    const float* atom  = (const float*)d_in[0];  // (n_nodes, 128)
    const float* esph  = (const float*)d_in[1];  // (n_edges, 64)
    const float* ks    = (const float*)d_in[3];  // (320, 128)
    const float* bs    = (const float*)d_in[4];  // (128,)
    const float* kg    = (const float*)d_in[5];  // (320, 128)
    const float* bg    = (const float*)d_in[6];  // (128,)
    const int*   pairs = (const int*)d_in[7];    // (n_edges, 2) int32

    int n_nodes = in_sizes[0] / ATOM_DIM;
    int n_edges = in_sizes[1] / 64;

    __half *p_edgebuf, *p_nodebuf, *p_W4T, *p_WeT;
    float *p_x, *p_bias;
    cudaGetSymbolAddress((void**)&p_edgebuf, g_edgebuf);
    cudaGetSymbolAddress((void**)&p_nodebuf, g_nodebuf);
    cudaGetSymbolAddress((void**)&p_x,       g_x);
    cudaGetSymbolAddress((void**)&p_W4T,     g_W4T);
    cudaGetSymbolAddress((void**)&p_WeT,     g_WeT);
    cudaGetSymbolAddress((void**)&p_bias,    g_biasPk);

    // dynamic smem: A tile + B chunk (+ bias for edge GEMM)
    const int SMEM_NODE = 2 * 128 * 128 * 2;               // 65536
    const int SMEM_EDGE = 2 * 128 * 64 * 2 + 256 * 4;      // 33792
    cudaFuncSetAttribute(gemm_mma<128, 512, false>,
                         cudaFuncAttributeMaxDynamicSharedMemorySize, SMEM_NODE);
    cudaFuncSetAttribute(gemm_mma<64, 256, true>,
                         cudaFuncAttributeMaxDynamicSharedMemorySize, SMEM_EDGE);

    // 1) pack weights (transpose + fp16)
    pack_weights<<<(512 * 128 + 256 * 64 + 256 + 255) / 256, 256>>>(ks, kg, bs, bg);

    // 2) edge contributions (step-invariant): Es|Eg = esph @ WeT^T + bias -> fp16
    gemm_mma<64, 256, true><<<n_edges / 128, 256, SMEM_EDGE>>>(esph, p_WeT, p_edgebuf, p_bias);

    // 3) init x and acc
    int n4 = n_nodes * (ATOM_DIM / 4);
    init_xa<<<(n4 + 255) / 256, 256>>>(atom, n4);

    // 4) three message-passing steps
    for (int s = 0; s < 3; s++) {
        gemm_mma<128, 512, false><<<(n_nodes + 127) / 128, 256, SMEM_NODE>>>(
            p_x, p_W4T, p_nodebuf, nullptr);
        edge_msg<<<(n_edges + 7) / 8, 256>>>(pairs, n_edges);
        finish<<<(n4 + 255) / 256, 256>>>((float*)d_out, n4, s == 2 ? 1 : 0);
    }
}